// round 2
// baseline (speedup 1.0000x reference)
#include <cuda_runtime.h>
#include <math.h>

#define Bsz 512
#define Tc  64
#define Ed  512
#define Vd  256

__device__ float g_xgates[67108864];   // (T,B,4E)
__device__ float g_gates [1048576];    // (B,4E)
__device__ float g_h0    [262144];
__device__ float g_c     [262144];
__device__ float g_hs    [16777216];   // (T,B,E)
__device__ float g_qc    [16777216];
__device__ float g_kc    [16777216];
__device__ float g_vc    [16777216];
__device__ float g_qt    [16777216];
__device__ float g_kt    [4194304];
__device__ float g_vt    [4194304];
__device__ float g_oc    [16777216];
__device__ float g_ot    [16777216];
__device__ float g_ca    [16777216];
__device__ float g_ta    [16777216];
__device__ float g_lg    [8388608];    // (T,B,V)

__device__ __forceinline__ void ffma2(unsigned long long& d, unsigned long long a,
                                      unsigned long long b) {
    asm("fma.rn.f32x2 %0, %1, %2, %0;" : "+l"(d) : "l"(a), "l"(b));
}
__device__ __forceinline__ unsigned long long pack2(float x, float y) {
    unsigned long long r;
    asm("mov.b64 %0, {%1, %2};" : "=l"(r) : "r"(__float_as_uint(x)), "r"(__float_as_uint(y)));
    return r;
}
__device__ __forceinline__ void unpack2(unsigned long long d, float& lo, float& hi) {
    unsigned int l, h;
    asm("mov.b64 {%0, %1}, %2;" : "=r"(l), "=r"(h) : "l"(d));
    lo = __uint_as_float(l); hi = __uint_as_float(h);
}
__device__ __forceinline__ float sigmoidf_(float x) { return 1.0f / (1.0f + expf(-x)); }

// Tiled fp32 GEMM (NT): C[M,N] = op(A[M,K] @ Bw[N,K]^T)
// MODE 0: C = alpha*(acc+bias[n])
// MODE 1: A(m,k): m->(t=m>>9,b=m&511); t==0 -> 0 else tos[b,t,k]. C=acc.
// MODE 2: C = acc + Dadd[m*N+n]
// MODE 3: A(m,k) = k<512 ? A[m,k] : A2[m,k-512]. C = acc + bias[n].
template <int MODE, int TBM, int TBN>
__global__ void __launch_bounds__(256) gemm_f32(
    float* __restrict__ C, const float* __restrict__ A, const float* __restrict__ A2,
    const float* __restrict__ Bw, const float* __restrict__ bias,
    const float* __restrict__ Dadd, int M, int N, int K, float alpha)
{
    constexpr int BK  = 16;
    constexpr int TM  = TBM / 16;
    constexpr int TN  = TBN / 16;
    constexpr int TMH = TM / 2;

    __shared__ float As[BK][TBM];
    __shared__ float Bs[BK][TBN];

    const int tid = threadIdx.x;
    const int m0  = blockIdx.y * TBM;
    const int n0  = blockIdx.x * TBN;
    const int ty  = tid >> 4;
    const int tx  = tid & 15;

    unsigned long long acc[TMH][TN];
#pragma unroll
    for (int i = 0; i < TMH; i++)
#pragma unroll
        for (int j = 0; j < TN; j++) acc[i][j] = 0ull;

    for (int k0 = 0; k0 < K; k0 += BK) {
#pragma unroll
        for (int it = 0; it < (TBM * 4) / 256; ++it) {
            int f = tid + it * 256;
            int r = f >> 2, c4 = (f & 3) << 2;
            int gm = m0 + r, gk = k0 + c4;
            float4 val;
            if constexpr (MODE == 1) {
                int tt = gm >> 9, bb = gm & 511;
                if (tt == 0) val = make_float4(0.f, 0.f, 0.f, 0.f);
                else val = *reinterpret_cast<const float4*>(A + (size_t)bb * 16384 + tt * 256 + gk);
            } else if constexpr (MODE == 3) {
                const float* src = (gk < 512) ? (A + (size_t)gm * 512 + gk)
                                              : (A2 + (size_t)gm * 512 + (gk - 512));
                val = *reinterpret_cast<const float4*>(src);
            } else {
                val = *reinterpret_cast<const float4*>(A + (size_t)gm * K + gk);
            }
            As[c4 + 0][r] = val.x; As[c4 + 1][r] = val.y;
            As[c4 + 2][r] = val.z; As[c4 + 3][r] = val.w;
        }
#pragma unroll
        for (int it = 0; it < (TBN * 4) / 256; ++it) {
            int f = tid + it * 256;
            int r = f >> 2, c4 = (f & 3) << 2;
            float4 val = *reinterpret_cast<const float4*>(Bw + (size_t)(n0 + r) * K + k0 + c4);
            Bs[c4 + 0][r] = val.x; Bs[c4 + 1][r] = val.y;
            Bs[c4 + 2][r] = val.z; Bs[c4 + 3][r] = val.w;
        }
        __syncthreads();

#pragma unroll
        for (int kk = 0; kk < BK; ++kk) {
            unsigned long long a2[TMH];
            const ulonglong2* ap = reinterpret_cast<const ulonglong2*>(&As[kk][ty * TM]);
#pragma unroll
            for (int i = 0; i < TMH / 2; i++) {
                ulonglong2 u = ap[i];
                a2[2 * i] = u.x; a2[2 * i + 1] = u.y;
            }
            float bf[TN];
            const float4* bp = reinterpret_cast<const float4*>(&Bs[kk][tx * TN]);
#pragma unroll
            for (int j = 0; j < TN / 4; j++) {
                float4 v4 = bp[j];
                bf[4*j] = v4.x; bf[4*j+1] = v4.y; bf[4*j+2] = v4.z; bf[4*j+3] = v4.w;
            }
            unsigned long long bd[TN];
#pragma unroll
            for (int j = 0; j < TN; j++) bd[j] = pack2(bf[j], bf[j]);
#pragma unroll
            for (int i = 0; i < TMH; i++)
#pragma unroll
                for (int j = 0; j < TN; j++) ffma2(acc[i][j], a2[i], bd[j]);
        }
        __syncthreads();
    }

#pragma unroll
    for (int i = 0; i < TMH; i++) {
        const int gm = m0 + ty * TM + 2 * i;
        float rlo[TN], rhi[TN];
#pragma unroll
        for (int j = 0; j < TN; j++) {
            float lo, hi;
            unpack2(acc[i][j], lo, hi);
            const int gn = n0 + tx * TN + j;
            if constexpr (MODE == 0) {
                float bia = bias ? bias[gn] : 0.f;
                lo = alpha * (lo + bia); hi = alpha * (hi + bia);
            } else if constexpr (MODE == 2) {
                lo += Dadd[(size_t)gm * N + gn];
                hi += Dadd[(size_t)(gm + 1) * N + gn];
            } else if constexpr (MODE == 3) {
                float bia = bias ? bias[gn] : 0.f;
                lo += bia; hi += bia;
            }
            rlo[j] = lo; rhi[j] = hi;
        }
#pragma unroll
        for (int j4 = 0; j4 < TN / 4; j4++) {
            int gn = n0 + tx * TN + 4 * j4;
            *reinterpret_cast<float4*>(&C[(size_t)gm * N + gn]) =
                make_float4(rlo[4*j4], rlo[4*j4+1], rlo[4*j4+2], rlo[4*j4+3]);
            *reinterpret_cast<float4*>(&C[(size_t)(gm + 1) * N + gn]) =
                make_float4(rhi[4*j4], rhi[4*j4+1], rhi[4*j4+2], rhi[4*j4+3]);
        }
    }
}

__global__ void __launch_bounds__(256) init_h0c0(
    const float* __restrict__ chn, const float* __restrict__ thn,
    const float* __restrict__ ccn, const float* __restrict__ tcn,
    float* __restrict__ h0, float* __restrict__ c0)
{
    int idx = blockIdx.x * 256 + threadIdx.x;
    int bb = idx >> 9, e = idx & 511;
    h0[idx] = (e < 256) ? chn[bb * 256 + e] : thn[bb * 256 + e - 256];
    c0[idx] = (e < 256) ? ccn[bb * 256 + e] : tcn[bb * 256 + e - 256];
}

__global__ void __launch_bounds__(256) lstm_update(
    const float* __restrict__ gates, const float* __restrict__ b_ih,
    const float* __restrict__ b_hh, float* __restrict__ c, float* __restrict__ h_out)
{
    int idx = blockIdx.x * 256 + threadIdx.x;
    int bb = idx >> 9, e = idx & 511;
    const float* g = gates + (size_t)bb * 2048;
    float gi = g[e]        + b_ih[e]        + b_hh[e];
    float gf = g[e + 512]  + b_ih[e + 512]  + b_hh[e + 512];
    float gg = g[e + 1024] + b_ih[e + 1024] + b_hh[e + 1024];
    float go = g[e + 1536] + b_ih[e + 1536] + b_hh[e + 1536];
    float cc = sigmoidf_(gf) * c[idx] + sigmoidf_(gi) * tanhf(gg);
    c[idx] = cc;
    h_out[idx] = sigmoidf_(go) * tanhf(cc);
}

// Fused attention per batch elem. q,o: (T,B,E); k,v: (B,S,E). Block = one b.
template <int S>
__global__ void __launch_bounds__(256) attn_kernel(
    const float* __restrict__ q, const float* __restrict__ k,
    const float* __restrict__ v, float* __restrict__ o)
{
    constexpr int TN = S / 16;
    __shared__ union SU {
        struct { float qs[16][64]; float ks[16][S]; } a;
        float vs[S][64];
    } u;
    __shared__ float sc[64][S];

    const int b = blockIdx.x;
    const int tid = threadIdx.x;
    const int ty = tid >> 4, tx = tid & 15;

    float acc[4][TN];
#pragma unroll
    for (int r = 0; r < 4; r++)
#pragma unroll
        for (int j = 0; j < TN; j++) acc[r][j] = 0.f;

    for (int k0 = 0; k0 < Ed; k0 += 16) {
        {
            int r = tid >> 2, c4 = (tid & 3) << 2;
            float4 val = *reinterpret_cast<const float4*>(q + ((size_t)r * Bsz + b) * Ed + k0 + c4);
            u.a.qs[c4+0][r] = val.x; u.a.qs[c4+1][r] = val.y;
            u.a.qs[c4+2][r] = val.z; u.a.qs[c4+3][r] = val.w;
        }
        if (tid < S * 4) {
            int r = tid >> 2, c4 = (tid & 3) << 2;
            float4 val = *reinterpret_cast<const float4*>(k + ((size_t)b * S + r) * Ed + k0 + c4);
            u.a.ks[c4+0][r] = val.x; u.a.ks[c4+1][r] = val.y;
            u.a.ks[c4+2][r] = val.z; u.a.ks[c4+3][r] = val.w;
        }
        __syncthreads();
#pragma unroll
        for (int kk = 0; kk < 16; kk++) {
            float av[4], bv[TN];
#pragma unroll
            for (int r = 0; r < 4; r++) av[r] = u.a.qs[kk][ty * 4 + r];
#pragma unroll
            for (int j = 0; j < TN; j++) bv[j] = u.a.ks[kk][tx * TN + j];
#pragma unroll
            for (int r = 0; r < 4; r++)
#pragma unroll
                for (int j = 0; j < TN; j++) acc[r][j] += av[r] * bv[j];
        }
        __syncthreads();
    }
#pragma unroll
    for (int r = 0; r < 4; r++)
#pragma unroll
        for (int j = 0; j < TN; j++) sc[ty * 4 + r][tx * TN + j] = acc[r][j];
    __syncthreads();

    if (tid < 64) {
        float mx = -3.4e38f;
        for (int s = 0; s < S; s++) mx = fmaxf(mx, sc[tid][s]);
        float sum = 0.f;
        for (int s = 0; s < S; s++) { float e = expf(sc[tid][s] - mx); sc[tid][s] = e; sum += e; }
        float inv = 1.f / sum;
        for (int s = 0; s < S; s++) sc[tid][s] *= inv;
    }
    __syncthreads();

    for (int n0 = 0; n0 < Ed; n0 += 64) {
#pragma unroll
        for (int it = 0; it < (S * 16) / 256; ++it) {
            int f = tid + it * 256;
            int r = f >> 4, c4 = (f & 15) << 2;
            *reinterpret_cast<float4*>(&u.vs[r][c4]) =
                *reinterpret_cast<const float4*>(v + ((size_t)b * S + r) * Ed + n0 + c4);
        }
        if (S == 16 && tid < 256) { /* single it covers all rows for S=16 */ }
        __syncthreads();
        float oa[4][4] = {};
        for (int sk = 0; sk < S; sk++) {
            float p[4];
#pragma unroll
            for (int r = 0; r < 4; r++) p[r] = sc[ty * 4 + r][sk];
            float4 vv = *reinterpret_cast<const float4*>(&u.vs[sk][tx * 4]);
            float vf[4] = {vv.x, vv.y, vv.z, vv.w};
#pragma unroll
            for (int r = 0; r < 4; r++)
#pragma unroll
                for (int j = 0; j < 4; j++) oa[r][j] += p[r] * vf[j];
        }
#pragma unroll
        for (int r = 0; r < 4; r++) {
            size_t base = ((size_t)(ty * 4 + r) * Bsz + b) * Ed + n0 + tx * 4;
            *reinterpret_cast<float4*>(&o[base]) = make_float4(oa[r][0], oa[r][1], oa[r][2], oa[r][3]);
        }
        __syncthreads();
    }
}

// Exact 1.5-entmax per row (V=256). logits (T,B,V) -> out (B,T,V).
__global__ void __launch_bounds__(256) entmax_kernel(
    const float* __restrict__ logits, float* __restrict__ out)
{
    __shared__ float s[256], cs1[256], cs2[256], taus[256], red[256];
    const int row = blockIdx.x;
    const int tid = threadIdx.x;

    float z = logits[(size_t)row * 256 + tid] * 0.5f;
    red[tid] = z;
    __syncthreads();
    for (int off = 128; off > 0; off >>= 1) {
        if (tid < off) red[tid] = fmaxf(red[tid], red[tid + off]);
        __syncthreads();
    }
    z -= red[0];
    __syncthreads();

    s[tid] = -z;
    __syncthreads();
    for (int kk = 2; kk <= 256; kk <<= 1) {
        for (int j = kk >> 1; j > 0; j >>= 1) {
            int ixj = tid ^ j;
            if (ixj > tid) {
                float a = s[tid], b2 = s[ixj];
                bool swp = ((tid & kk) == 0) ? (a > b2) : (a < b2);
                if (swp) { s[tid] = b2; s[ixj] = a; }
            }
            __syncthreads();
        }
    }
    float zs = -s[tid];

    cs1[tid] = zs; cs2[tid] = zs * zs;
    __syncthreads();
    for (int off = 1; off < 256; off <<= 1) {
        float a1 = 0.f, a2 = 0.f;
        if (tid >= off) { a1 = cs1[tid - off]; a2 = cs2[tid - off]; }
        __syncthreads();
        if (tid >= off) { cs1[tid] += a1; cs2[tid] += a2; }
        __syncthreads();
    }

    float rho   = (float)(tid + 1);
    float mean  = cs1[tid] / rho;
    float msq   = cs2[tid] / rho;
    float ssv   = rho * (msq - mean * mean);
    float delta = (1.0f - ssv) / rho;
    float sq    = (delta > 0.f) ? sqrtf(delta) : 0.f;
    float tau   = mean - sq;
    taus[tid] = tau;
    red[tid]  = (tau <= zs) ? 1.f : 0.f;
    __syncthreads();
    for (int off = 128; off > 0; off >>= 1) {
        if (tid < off) red[tid] += red[tid + off];
        __syncthreads();
    }
    int kcnt = (int)red[0];
    float tau_star = taus[kcnt - 1];
    float y = fmaxf(z - tau_star, 0.f);
    int t = row >> 9, b = row & 511;
    out[((size_t)b * Tc + t) * Vd + tid] = y * y;
}

extern "C" void kernel_launch(void* const* d_in, const int* in_sizes, int n_in,
                              void* d_out, int out_size)
{
    const float* char_enc = (const float*)d_in[0];
    const float* char_hn0 = (const float*)d_in[1];
    const float* char_cn0 = (const float*)d_in[2];
    const float* tag_enc  = (const float*)d_in[3];
    const float* tag_hn0  = (const float*)d_in[4];
    const float* tag_cn0  = (const float*)d_in[5];
    const float* tos      = (const float*)d_in[6];
    const float* w_ih     = (const float*)d_in[7];
    const float* w_hh     = (const float*)d_in[8];
    const float* b_ih     = (const float*)d_in[9];
    const float* b_hh     = (const float*)d_in[10];
    const float* cwq = (const float*)d_in[11];
    const float* cwk = (const float*)d_in[12];
    const float* cwv = (const float*)d_in[13];
    const float* cbq = (const float*)d_in[14];
    const float* cbk = (const float*)d_in[15];
    const float* cbv = (const float*)d_in[16];
    const float* cwo = (const float*)d_in[17];
    const float* cbo = (const float*)d_in[18];
    const float* twq = (const float*)d_in[19];
    const float* twk = (const float*)d_in[20];
    const float* twv = (const float*)d_in[21];
    const float* tbq = (const float*)d_in[22];
    const float* tbk = (const float*)d_in[23];
    const float* tbv = (const float*)d_in[24];
    const float* two_ = (const float*)d_in[25];
    const float* tbo = (const float*)d_in[26];
    const float* out_w = (const float*)d_in[27];
    const float* out_b = (const float*)d_in[28];
    float* out = (float*)d_out;

    float *xg, *gates, *h0, *c0, *hs, *qc, *kc, *vc, *qt, *kt, *vt, *oc, *ot, *ca, *ta, *lg;
    cudaGetSymbolAddress((void**)&xg,    g_xgates);
    cudaGetSymbolAddress((void**)&gates, g_gates);
    cudaGetSymbolAddress((void**)&h0,    g_h0);
    cudaGetSymbolAddress((void**)&c0,    g_c);
    cudaGetSymbolAddress((void**)&hs,    g_hs);
    cudaGetSymbolAddress((void**)&qc,    g_qc);
    cudaGetSymbolAddress((void**)&kc,    g_kc);
    cudaGetSymbolAddress((void**)&vc,    g_vc);
    cudaGetSymbolAddress((void**)&qt,    g_qt);
    cudaGetSymbolAddress((void**)&kt,    g_kt);
    cudaGetSymbolAddress((void**)&vt,    g_vt);
    cudaGetSymbolAddress((void**)&oc,    g_oc);
    cudaGetSymbolAddress((void**)&ot,    g_ot);
    cudaGetSymbolAddress((void**)&ca,    g_ca);
    cudaGetSymbolAddress((void**)&ta,    g_ta);
    cudaGetSymbolAddress((void**)&lg,    g_lg);

    const float qscale = 1.0f / sqrtf(512.0f);

    // h0/c0
    init_h0c0<<<1024, 256>>>(char_hn0, tag_hn0, char_cn0, tag_cn0, h0, c0);

    // x-side gates for all T at once: (32768, 2048) = xs @ w_ih^T
    {
        dim3 g(2048 / 64, 32768 / 128);
        gemm_f32<1, 128, 64><<<g, 256>>>(xg, tos, nullptr, w_ih, nullptr, nullptr,
                                         32768, 2048, 256, 1.0f);
    }

    // Sequential LSTM
    for (int t = 0; t < 64; t++) {
        const float* hprev = (t == 0) ? h0 : (hs + (size_t)(t - 1) * 262144);
        dim3 g(2048 / 64, 512 / 128);
        gemm_f32<2, 128, 64><<<g, 256>>>(gates, hprev, nullptr, w_hh, nullptr,
                                         xg + (size_t)t * 1048576, 512, 2048, 512, 1.0f);
        lstm_update<<<1024, 256>>>(gates, b_ih, b_hh, c0, hs + (size_t)t * 262144);
    }

    // Projections
    dim3 gBig(512 / 64, 32768 / 128);
    gemm_f32<0, 128, 64><<<gBig, 256>>>(qc, hs, nullptr, cwq, cbq, nullptr, 32768, 512, 512, qscale);
    gemm_f32<0, 128, 64><<<gBig, 256>>>(qt, hs, nullptr, twq, tbq, nullptr, 32768, 512, 512, qscale);
    gemm_f32<0, 128, 64><<<gBig, 256>>>(kc, char_enc, nullptr, cwk, cbk, nullptr, 32768, 512, 512, 1.0f);
    gemm_f32<0, 128, 64><<<gBig, 256>>>(vc, char_enc, nullptr, cwv, cbv, nullptr, 32768, 512, 512, 1.0f);
    dim3 gTag(512 / 64, 8192 / 128);
    gemm_f32<0, 128, 64><<<gTag, 256>>>(kt, tag_enc, nullptr, twk, tbk, nullptr, 8192, 512, 512, 1.0f);
    gemm_f32<0, 128, 64><<<gTag, 256>>>(vt, tag_enc, nullptr, twv, tbv, nullptr, 8192, 512, 512, 1.0f);

    // Attention
    attn_kernel<64><<<512, 256>>>(qc, kc, vc, oc);
    attn_kernel<16><<<512, 256>>>(qt, kt, vt, ot);

    // Output projections of attention
    gemm_f32<0, 128, 64><<<gBig, 256>>>(ca, oc, nullptr, cwo, cbo, nullptr, 32768, 512, 512, 1.0f);
    gemm_f32<0, 128, 64><<<gBig, 256>>>(ta, ot, nullptr, two_, tbo, nullptr, 32768, 512, 512, 1.0f);

    // logits = concat(ca, ta) @ out_w^T + out_b : (32768, 256), K=1024
    {
        dim3 g(256 / 64, 32768 / 128);
        gemm_f32<3, 128, 64><<<g, 256>>>(lg, ca, ta, out_w, out_b, nullptr, 32768, 256, 1024, 1.0f);
    }

    // entmax + transpose to (B,T,V)
    entmax_kernel<<<32768, 256>>>(lg, out);
}